// round 15
// baseline (speedup 1.0000x reference)
#include <cuda_runtime.h>
#include <cuda_bf16.h>
#include <cstdint>

typedef unsigned int u32;

#define BB 2
#define SS 2048
#define DD 1024
#define HH 16
#define HD 64
#define MM 4096
#define LOG2E 1.4426950408889634f

__device__ float g_q[MM * DD];
__device__ float g_k[MM * DD];
__device__ float g_v[MM * DD];
__device__ float g_mask[BB * SS];
__device__ int   g_maskflag;
// pre-split operands (bf16x2 hi/lo packs along k)
__device__ u32 g_xh[MM * DD / 2];   // x    [m][kpair]
__device__ u32 g_xl[MM * DD / 2];
__device__ u32 g_wh[4 * DD * DD / 2]; // Wq,Wk,Wv,Wo [n][kpair]
__device__ u32 g_wl[4 * DD * DD / 2];
__device__ u32 g_ah[MM * DD / 2];   // attn out [m][kpair] (written split by flash)
__device__ u32 g_al[MM * DD / 2];
// pre-split K/V for flash (flash-native layouts)
__device__ u32 g_kh[MM * DD / 2];   // [bh][s][dpair]
__device__ u32 g_kl[MM * DD / 2];
__device__ u32 g_vh[MM * DD / 2];   // [bh][jpair][n]
__device__ u32 g_vl[MM * DD / 2];

// ---------------------------------------------------------------------------
// Mask detect / repack (proven)
// ---------------------------------------------------------------------------
__global__ void detect_mask_kernel(const unsigned char* __restrict__ p) {
    __shared__ int f1, f23, f4;
    int tid = threadIdx.x;
    if (tid == 0) { f1 = 0; f23 = 0; f4 = 0; }
    __syncthreads();
    int l1 = 0, l23 = 0, l4 = 0;
    for (int i = tid; i < BB * SS; i += blockDim.x) {
        unsigned char v = p[i];
        if (v) {
            int r = i & 3;
            if (r == 1) l1 = 1;
            else if (r == 2 || r == 3) l23 = 1;
            if ((i & 7) == 4) l4 = 1;
        }
    }
    if (l1)  atomicOr(&f1, 1);
    if (l23) atomicOr(&f23, 1);
    if (l4)  atomicOr(&f4, 1);
    __syncthreads();
    if (tid == 0) {
        int flag;
        if (f1) flag = 0;
        else if (f23) flag = 2;
        else if (f4) flag = 1;
        else flag = 3;
        g_maskflag = flag;
    }
}

__global__ void repack_mask_kernel(const void* __restrict__ p) {
    int i = blockIdx.x * blockDim.x + threadIdx.x;
    if (i >= BB * SS) return;
    int flag = g_maskflag;
    bool mv;
    if (flag == 0)      mv = ((const unsigned char*)p)[i] != 0;
    else if (flag == 1) mv = ((const int*)p)[i] != 0;
    else if (flag == 2) mv = ((const float*)p)[i] != 0.0f;
    else                mv = ((const long long*)p)[i] != 0;
    g_mask[i] = mv ? -1.0e9f : 0.0f;
}

// ---------------------------------------------------------------------------
// bf16 helpers
// ---------------------------------------------------------------------------
__device__ __forceinline__ void bsplit(float a, float b, u32& h, u32& l) {
    __nv_bfloat162 hh = __floats2bfloat162_rn(a, b);
    float ra_ = a - __bfloat162float(hh.x);
    float rb_ = b - __bfloat162float(hh.y);
    __nv_bfloat162 ll = __floats2bfloat162_rn(ra_, rb_);
    h = *(u32*)&hh; l = *(u32*)&ll;
}
__device__ __forceinline__ void mma16(float* c, const u32* a, const u32* b) {
    asm volatile("mma.sync.aligned.m16n8k16.row.col.f32.bf16.bf16.f32 "
        "{%0,%1,%2,%3}, {%4,%5,%6,%7}, {%8,%9}, {%0,%1,%2,%3};"
        : "+f"(c[0]), "+f"(c[1]), "+f"(c[2]), "+f"(c[3])
        : "r"(a[0]), "r"(a[1]), "r"(a[2]), "r"(a[3]), "r"(b[0]), "r"(b[1]));
}
__device__ __forceinline__ u32 smaddr(const u32* p) {
    return (u32)__cvta_generic_to_shared(p);
}
__device__ __forceinline__ void cpasync16(u32 sdst, const u32* gsrc) {
    asm volatile("cp.async.ca.shared.global [%0], [%1], 16;"
        :: "r"(sdst), "l"(gsrc) : "memory");
}
#define CP_COMMIT() asm volatile("cp.async.commit_group;" ::: "memory")
#define CP_WAIT1()  asm volatile("cp.async.wait_group 1;" ::: "memory")
#define CP_WAIT0()  asm volatile("cp.async.wait_group 0;" ::: "memory")

// ---------------------------------------------------------------------------
// Pre-split x and the 4 weight matrices into bf16 hi/lo packs (pairs along k)
// ---------------------------------------------------------------------------
__global__ void repack_inputs(const float* __restrict__ x,
                              const float* __restrict__ Wq, const float* __restrict__ Wk,
                              const float* __restrict__ Wv, const float* __restrict__ Wo) {
    int i = blockIdx.x * 256 + threadIdx.x;   // 0 .. 4M-1
    if (i < 2097152) {
        const float* s = x + 2 * (size_t)i;
        u32 h, l; bsplit(s[0], s[1], h, l);
        g_xh[i] = h; g_xl[i] = l;
    } else {
        int j = i - 2097152;
        int z = j >> 19, p = j & 524287;
        const float* W = (z == 0) ? Wq : (z == 1 ? Wk : (z == 2 ? Wv : Wo));
        const float* s = W + 2 * (size_t)p;
        u32 h, l; bsplit(s[0], s[1], h, l);
        g_wh[(size_t)z * 524288 + p] = h;
        g_wl[(size_t)z * 524288 + p] = l;
    }
}

// ---------------------------------------------------------------------------
// Repack K/V into flash-native pre-split layouts (proven R13)
// ---------------------------------------------------------------------------
__global__ void repack_kv() {
    int i = blockIdx.x * 256 + threadIdx.x;   // 0 .. 2M-1
    {
        int row = i >> 5, dp = i & 31;
        const float* kp = g_k + ((size_t)row << 6) + (dp << 1);
        u32 h, l; bsplit(kp[0], kp[1], h, l);
        g_kh[i] = h; g_kl[i] = l;
    }
    {
        const float* vp = g_v + ((size_t)(i >> 6) << 7) + (i & 63);
        u32 h, l; bsplit(vp[0], vp[64], h, l);
        g_vh[i] = h; g_vl[i] = l;
    }
}

// ---------------------------------------------------------------------------
// Split-BF16 GEMM, pre-split operands + cp.async double buffer.
// CTA 128m x 256n, 8 warps of 64x64 (wm=(wid&1)*64, wn=(wid>>1)*64).
// mode 0: A = g_xh/g_xl, W/bias/dst by blockIdx.z (g_q/g_k/g_v permuted).
// mode 1: A = g_ah/g_al, W = Wo slot, dst = Cout plain [M,N].
// ---------------------------------------------------------------------------
#define SRU 20
#define GA_TU (128 * SRU)               // 2560 u32
#define GB_TU (256 * SRU)               // 5120 u32
#define GBUF (2 * GA_TU + 2 * GB_TU)    // 15360 u32
#define GSM_BYTES (2 * GBUF * 4)        // 122880

__global__ __launch_bounds__(256, 1)
void gemm_cp(const float* __restrict__ bq, const float* __restrict__ bk,
             const float* __restrict__ bv, const float* __restrict__ bo,
             float* __restrict__ Cout, int mode)
{
    extern __shared__ u32 sm[];

    int z = (mode == 0) ? (int)blockIdx.z : 3;
    const u32* Ah = (mode == 0) ? g_xh : g_ah;
    const u32* Al = (mode == 0) ? g_xl : g_al;
    const u32* Wh = g_wh + (size_t)z * 524288;
    const u32* Wl = g_wl + (size_t)z * 524288;
    const float* bias = (mode == 1) ? bo : (z == 0 ? bq : (z == 1 ? bk : bv));
    float* C = (mode == 1) ? Cout : (z == 0 ? g_q : (z == 1 ? g_k : g_v));

    int tid = threadIdx.x, wid = tid >> 5, lane = tid & 31;
    int gid = lane >> 2, tig = lane & 3;
    int m0 = (int)blockIdx.y << 7, n0 = (int)blockIdx.x << 8;
    int wm = (wid & 1) * 64, wn = (wid >> 1) * 64;

    // copy coords: A rows 0..127 (2 half-rows/thread), B rows 0..255
    int crA = tid >> 1, cu = (tid & 1) * 8;
    const u32* pAh = Ah + (size_t)(m0 + crA) * 512 + cu;
    const u32* pAl = Al + (size_t)(m0 + crA) * 512 + cu;
    int crB0 = tid >> 1, crB1 = (tid >> 1) + 128;
    const u32* pBh0 = Wh + (size_t)(n0 + crB0) * 512 + cu;
    const u32* pBh1 = Wh + (size_t)(n0 + crB1) * 512 + cu;
    const u32* pBl0 = Wl + (size_t)(n0 + crB0) * 512 + cu;
    const u32* pBl1 = Wl + (size_t)(n0 + crB1) * 512 + cu;

    u32 sb = smaddr(sm);
    u32 soA = (u32)(crA * SRU + cu) * 4;
    u32 soB0 = (u32)(crB0 * SRU + cu) * 4;
    u32 soB1 = (u32)(crB1 * SRU + cu) * 4;

    float acc[4][8][4];
#pragma unroll
    for (int mt = 0; mt < 4; mt++)
#pragma unroll
        for (int nt = 0; nt < 8; nt++)
#pragma unroll
            for (int i = 0; i < 4; i++) acc[mt][nt][i] = 0.0f;

    // prologue: tile 0 -> buf 0
    {
        u32 d = sb;
        cpasync16(d + soA, pAh);                    cpasync16(d + soA + 16, pAh + 4);
        cpasync16(d + GA_TU * 4 + soA, pAl);        cpasync16(d + GA_TU * 4 + soA + 16, pAl + 4);
        u32 bB = d + 2 * GA_TU * 4;
        cpasync16(bB + soB0, pBh0);                 cpasync16(bB + soB0 + 16, pBh0 + 4);
        cpasync16(bB + soB1, pBh1);                 cpasync16(bB + soB1 + 16, pBh1 + 4);
        u32 bL = bB + GB_TU * 4;
        cpasync16(bL + soB0, pBl0);                 cpasync16(bL + soB0 + 16, pBl0 + 4);
        cpasync16(bL + soB1, pBl1);                 cpasync16(bL + soB1 + 16, pBl1 + 4);
        CP_COMMIT();
    }

    const int nk = DD / 32;
    for (int kt = 0; kt < nk; kt++) {
        int cur = kt & 1;
        if (kt + 1 < nk) {
            int ko = (kt + 1) * 16;
            u32 d = sb + (cur ^ 1) * GBUF * 4;
            cpasync16(d + soA, pAh + ko);                 cpasync16(d + soA + 16, pAh + ko + 4);
            cpasync16(d + GA_TU * 4 + soA, pAl + ko);     cpasync16(d + GA_TU * 4 + soA + 16, pAl + ko + 4);
            u32 bB = d + 2 * GA_TU * 4;
            cpasync16(bB + soB0, pBh0 + ko);              cpasync16(bB + soB0 + 16, pBh0 + ko + 4);
            cpasync16(bB + soB1, pBh1 + ko);              cpasync16(bB + soB1 + 16, pBh1 + ko + 4);
            u32 bL = bB + GB_TU * 4;
            cpasync16(bL + soB0, pBl0 + ko);              cpasync16(bL + soB0 + 16, pBl0 + ko + 4);
            cpasync16(bL + soB1, pBl1 + ko);              cpasync16(bL + soB1 + 16, pBl1 + ko + 4);
            CP_COMMIT();
            CP_WAIT1();
        } else {
            CP_WAIT0();
        }
        __syncthreads();

        const u32* sAh = sm + cur * GBUF;
        const u32* sAl = sAh + GA_TU;
        const u32* sBh = sAh + 2 * GA_TU;
        const u32* sBl = sBh + GB_TU;

#pragma unroll
        for (int ks = 0; ks < 2; ks++) {
            int ko = ks * 8;
            u32 ah[4][4], al[4][4];
#pragma unroll
            for (int mt = 0; mt < 4; mt++) {
                int base = (wm + mt * 16 + gid) * SRU + ko + tig;
                ah[mt][0] = sAh[base];
                ah[mt][1] = sAh[base + 8 * SRU];
                ah[mt][2] = sAh[base + 4];
                ah[mt][3] = sAh[base + 8 * SRU + 4];
                al[mt][0] = sAl[base];
                al[mt][1] = sAl[base + 8 * SRU];
                al[mt][2] = sAl[base + 4];
                al[mt][3] = sAl[base + 8 * SRU + 4];
            }
#pragma unroll
            for (int hf = 0; hf < 2; hf++) {
                u32 bh[4][2], bl[4][2];
#pragma unroll
                for (int q = 0; q < 4; q++) {
                    int nt = hf * 4 + q;
                    int base = (wn + nt * 8 + gid) * SRU + ko + tig;
                    bh[q][0] = sBh[base];
                    bh[q][1] = sBh[base + 4];
                    bl[q][0] = sBl[base];
                    bl[q][1] = sBl[base + 4];
                }
#pragma unroll
                for (int mt = 0; mt < 4; mt++)
#pragma unroll
                    for (int q = 0; q < 4; q++) {
                        float* a_ = acc[mt][hf * 4 + q];
                        mma16(a_, ah[mt], bh[q]);
                        mma16(a_, ah[mt], bl[q]);
                        mma16(a_, al[mt], bh[q]);
                    }
            }
        }
        __syncthreads();
    }

#pragma unroll
    for (int mt = 0; mt < 4; mt++)
#pragma unroll
        for (int nt = 0; nt < 8; nt++) {
            int m = m0 + wm + mt * 16 + gid;
            int n = n0 + wn + nt * 8 + tig * 2;
            float b0 = bias[n], b1 = bias[n + 1];
            float2 p0 = make_float2(acc[mt][nt][0] + b0, acc[mt][nt][1] + b1);
            float2 p1 = make_float2(acc[mt][nt][2] + b0, acc[mt][nt][3] + b1);
            if (mode == 1) {
                *(float2*)&C[(size_t)m * DD + n] = p0;
                *(float2*)&C[(size_t)(m + 8) * DD + n] = p1;
            } else {
                int h = n >> 6, hd = n & 63;
                int b_ = m >> 11, s = m & 2047;
                *(float2*)&C[(((size_t)(b_ * 16 + h)) * SS + s) * HD + hd] = p0;
                int b2 = (m + 8) >> 11, s2 = (m + 8) & 2047;
                *(float2*)&C[(((size_t)(b2 * 16 + h)) * SS + s2) * HD + hd] = p1;
            }
        }
}

// ---------------------------------------------------------------------------
// Split-BF16 flash attention, cp.async double-buffered pre-split K/V
// (proven R13). Epilogue now writes pre-split g_ah/g_al for the out-proj.
// ---------------------------------------------------------------------------
#define KSTR 36
#define VSTR 72
#define FBUF 9216
#define FSM_BYTES (2 * FBUF * 4)

__global__ __launch_bounds__(256, 1)
void flash_mma()
{
    extern __shared__ u32 smd[];

    int tid = threadIdx.x, wid = tid >> 5, lane = tid & 31;
    int gid = lane >> 2, tig = lane & 3;
    int bh = blockIdx.y, b = bh >> 4, h = bh & 15;
    int qt = (int)gridDim.x - 1 - (int)blockIdx.x;
    int q0 = qt << 7;

    const u32* Khb = g_kh + (size_t)bh * SS * 32;
    const u32* Klb = g_kl + (size_t)bh * SS * 32;
    const u32* Vhb = g_vh + (size_t)bh * (SS / 2) * 64;
    const u32* Vlb = g_vl + (size_t)bh * (SS / 2) * 64;

    int kc0 = tid * 2, kc1 = tid * 2 + 1;
    int kr0 = kc0 >> 3, kcol0 = (kc0 & 7) * 4;
    int kr1 = kc1 >> 3, kcol1 = (kc1 & 7) * 4;
    int vp0 = kc0 >> 4, vcol0 = (kc0 & 15) * 4;
    int vp1 = kc1 >> 4, vcol1 = (kc1 & 15) * 4;

    u32 sb = smaddr(smd);

    int r0 = wid * 16 + gid;
    int grow0 = q0 + r0;

    u32 qh[4][4], ql[4][4];
    {
        const float* q0p = g_q + ((size_t)bh * SS + grow0) * HD;
        const float* q1p = q0p + 8 * HD;
#pragma unroll
        for (int ks = 0; ks < 4; ks++) {
            int c = 16 * ks + 2 * tig;
            float2 f0 = *(const float2*)(q0p + c);
            float2 f1 = *(const float2*)(q1p + c);
            float2 f2 = *(const float2*)(q0p + c + 8);
            float2 f3 = *(const float2*)(q1p + c + 8);
            bsplit(f0.x, f0.y, qh[ks][0], ql[ks][0]);
            bsplit(f1.x, f1.y, qh[ks][1], ql[ks][1]);
            bsplit(f2.x, f2.y, qh[ks][2], ql[ks][2]);
            bsplit(f3.x, f3.y, qh[ks][3], ql[ks][3]);
        }
    }

    float mi0 = -1e30f, mi1 = -1e30f, li0 = 0.0f, li1 = 0.0f;
    float o[8][4];
#pragma unroll
    for (int nt = 0; nt < 8; nt++)
#pragma unroll
        for (int i = 0; i < 4; i++) o[nt][i] = 0.0f;

    int jmax = 2 * qt + 1;

    {
        u32 d = sb;
        cpasync16(d + (kr0 * KSTR + kcol0) * 4, Khb + kr0 * 32 + kcol0);
        cpasync16(d + (kr1 * KSTR + kcol1) * 4, Khb + kr1 * 32 + kcol1);
        cpasync16(d + (2304 + kr0 * KSTR + kcol0) * 4, Klb + kr0 * 32 + kcol0);
        cpasync16(d + (2304 + kr1 * KSTR + kcol1) * 4, Klb + kr1 * 32 + kcol1);
        cpasync16(d + (4608 + vp0 * VSTR + vcol0) * 4, Vhb + vp0 * 64 + vcol0);
        cpasync16(d + (4608 + vp1 * VSTR + vcol1) * 4, Vhb + vp1 * 64 + vcol1);
        cpasync16(d + (6912 + vp0 * VSTR + vcol0) * 4, Vlb + vp0 * 64 + vcol0);
        cpasync16(d + (6912 + vp1 * VSTR + vcol1) * 4, Vlb + vp1 * 64 + vcol1);
        CP_COMMIT();
    }

    for (int jt = 0; jt <= jmax; jt++) {
        int cur = jt & 1;
        if (jt + 1 <= jmax) {
            int j1 = (jt + 1) << 6;
            const u32* kh = Khb + j1 * 32;
            const u32* kl = Klb + j1 * 32;
            const u32* vh = Vhb + (j1 >> 1) * 64;
            const u32* vl = Vlb + (j1 >> 1) * 64;
            u32 d = sb + (cur ^ 1) * FBUF * 4;
            cpasync16(d + (kr0 * KSTR + kcol0) * 4, kh + kr0 * 32 + kcol0);
            cpasync16(d + (kr1 * KSTR + kcol1) * 4, kh + kr1 * 32 + kcol1);
            cpasync16(d + (2304 + kr0 * KSTR + kcol0) * 4, kl + kr0 * 32 + kcol0);
            cpasync16(d + (2304 + kr1 * KSTR + kcol1) * 4, kl + kr1 * 32 + kcol1);
            cpasync16(d + (4608 + vp0 * VSTR + vcol0) * 4, vh + vp0 * 64 + vcol0);
            cpasync16(d + (4608 + vp1 * VSTR + vcol1) * 4, vh + vp1 * 64 + vcol1);
            cpasync16(d + (6912 + vp0 * VSTR + vcol0) * 4, vl + vp0 * 64 + vcol0);
            cpasync16(d + (6912 + vp1 * VSTR + vcol1) * 4, vl + vp1 * 64 + vcol1);
            CP_COMMIT();
            CP_WAIT1();
        } else {
            CP_WAIT0();
        }
        __syncthreads();

        int j0 = jt << 6;
        bool active = (j0 <= q0 + wid * 16 + 15);
        if (active) {
            const u32* sKh = smd + cur * FBUF;
            const u32* sKl = sKh + 2304;
            const u32* sVh = sKh + 4608;
            const u32* sVl = sKh + 6912;

            float s[8][4];
#pragma unroll
            for (int nt = 0; nt < 8; nt++)
#pragma unroll
                for (int i = 0; i < 4; i++) s[nt][i] = 0.0f;
#pragma unroll
            for (int ks = 0; ks < 4; ks++) {
#pragma unroll
                for (int nt = 0; nt < 8; nt++) {
                    int kr = (nt * 8 + gid) * KSTR + 8 * ks + tig;
                    u32 kb[2], kl2[2];
                    kb[0]  = sKh[kr];
                    kb[1]  = sKh[kr + 4];
                    kl2[0] = sKl[kr];
                    kl2[1] = sKl[kr + 4];
                    mma16(s[nt], qh[ks], kb);
                    mma16(s[nt], qh[ks], kl2);
                    mma16(s[nt], ql[ks], kb);
                }
            }

            bool applyC = (j0 + 63 > q0 + wid * 16);
            const float* mrow = g_mask + b * SS + j0;
#pragma unroll
            for (int nt = 0; nt < 8; nt++) {
                int cc = nt * 8 + 2 * tig;
                float2 md = *(const float2*)(mrow + cc);
                int gc0 = j0 + cc, gc1 = gc0 + 1;
                float v0 = s[nt][0] * 0.125f + md.x;
                float v1 = s[nt][1] * 0.125f + md.y;
                float v2 = s[nt][2] * 0.125f + md.x;
                float v3 = s[nt][3] * 0.125f + md.y;
                if (applyC) {
                    if (gc0 > grow0)     v0 = -1.0e9f;
                    if (gc1 > grow0)     v1 = -1.0e9f;
                    if (gc0 > grow0 + 8) v2 = -1.0e9f;
                    if (gc1 > grow0 + 8) v3 = -1.0e9f;
                }
                s[nt][0] = v0; s[nt][1] = v1; s[nt][2] = v2; s[nt][3] = v3;
            }

            float rm0 = -1e30f, rm1 = -1e30f;
#pragma unroll
            for (int nt = 0; nt < 8; nt++) {
                rm0 = fmaxf(rm0, fmaxf(s[nt][0], s[nt][1]));
                rm1 = fmaxf(rm1, fmaxf(s[nt][2], s[nt][3]));
            }
            rm0 = fmaxf(rm0, __shfl_xor_sync(0xffffffffu, rm0, 1));
            rm0 = fmaxf(rm0, __shfl_xor_sync(0xffffffffu, rm0, 2));
            rm1 = fmaxf(rm1, __shfl_xor_sync(0xffffffffu, rm1, 1));
            rm1 = fmaxf(rm1, __shfl_xor_sync(0xffffffffu, rm1, 2));
            float mn0 = fmaxf(mi0, rm0), mn1 = fmaxf(mi1, rm1);
            float c0 = exp2f((mi0 - mn0) * LOG2E), c1 = exp2f((mi1 - mn1) * LOG2E);
            mi0 = mn0; mi1 = mn1;
            float rs0 = 0.0f, rs1 = 0.0f;
#pragma unroll
            for (int nt = 0; nt < 8; nt++) {
                s[nt][0] = exp2f((s[nt][0] - mn0) * LOG2E);
                s[nt][1] = exp2f((s[nt][1] - mn0) * LOG2E);
                s[nt][2] = exp2f((s[nt][2] - mn1) * LOG2E);
                s[nt][3] = exp2f((s[nt][3] - mn1) * LOG2E);
                rs0 += s[nt][0] + s[nt][1];
                rs1 += s[nt][2] + s[nt][3];
            }
            rs0 += __shfl_xor_sync(0xffffffffu, rs0, 1);
            rs0 += __shfl_xor_sync(0xffffffffu, rs0, 2);
            rs1 += __shfl_xor_sync(0xffffffffu, rs1, 1);
            rs1 += __shfl_xor_sync(0xffffffffu, rs1, 2);
            li0 = li0 * c0 + rs0;
            li1 = li1 * c1 + rs1;
#pragma unroll
            for (int nt = 0; nt < 8; nt++) {
                o[nt][0] *= c0; o[nt][1] *= c0;
                o[nt][2] *= c1; o[nt][3] *= c1;
            }

#pragma unroll
            for (int ks = 0; ks < 4; ks++) {
                u32 ph[4], pl[4];
                bsplit(s[2 * ks][0],     s[2 * ks][1],     ph[0], pl[0]);
                bsplit(s[2 * ks][2],     s[2 * ks][3],     ph[1], pl[1]);
                bsplit(s[2 * ks + 1][0], s[2 * ks + 1][1], ph[2], pl[2]);
                bsplit(s[2 * ks + 1][2], s[2 * ks + 1][3], ph[3], pl[3]);
#pragma unroll
                for (int nt = 0; nt < 8; nt++) {
                    int vr = (8 * ks + tig) * VSTR + nt * 8 + gid;
                    u32 vb[2], vl2[2];
                    vb[0]  = sVh[vr];
                    vb[1]  = sVh[vr + 4 * VSTR];
                    vl2[0] = sVl[vr];
                    vl2[1] = sVl[vr + 4 * VSTR];
                    mma16(o[nt], ph, vb);
                    mma16(o[nt], pl, vb);
                    mma16(o[nt], ph, vl2);
                }
            }
        }
        __syncthreads();
    }

    // epilogue: write PRE-SPLIT attn output for the out-projection GEMM
    float i0 = 1.0f / li0, i1 = 1.0f / li1;
    size_t mr0 = (size_t)(b * SS + grow0) * 512;
    size_t mr1 = (size_t)(b * SS + grow0 + 8) * 512;
#pragma unroll
    for (int nt = 0; nt < 8; nt++) {
        int cp = (h << 5) + nt * 4 + tig;
        u32 hh, ll;
        bsplit(o[nt][0] * i0, o[nt][1] * i0, hh, ll);
        g_ah[mr0 + cp] = hh; g_al[mr0 + cp] = ll;
        bsplit(o[nt][2] * i1, o[nt][3] * i1, hh, ll);
        g_ah[mr1 + cp] = hh; g_al[mr1 + cp] = ll;
    }
}

// ---------------------------------------------------------------------------
extern "C" void kernel_launch(void* const* d_in, const int* in_sizes, int n_in,
                              void* d_out, int out_size) {
    const float* x  = (const float*)d_in[0];
    const void*  pm = d_in[1];
    const float* Wq = (const float*)d_in[2];
    const float* bq = (const float*)d_in[3];
    const float* Wk = (const float*)d_in[4];
    const float* bk = (const float*)d_in[5];
    const float* Wv = (const float*)d_in[6];
    const float* bv = (const float*)d_in[7];
    const float* Wo = (const float*)d_in[8];
    const float* bo = (const float*)d_in[9];
    float* out = (float*)d_out;

    cudaFuncSetAttribute(gemm_cp, cudaFuncAttributeMaxDynamicSharedMemorySize, GSM_BYTES);
    cudaFuncSetAttribute(flash_mma, cudaFuncAttributeMaxDynamicSharedMemorySize, FSM_BYTES);

    detect_mask_kernel<<<1, 256>>>((const unsigned char*)pm);
    repack_mask_kernel<<<16, 256>>>(pm);
    repack_inputs<<<16384, 256>>>(x, Wq, Wk, Wv, Wo);

    dim3 gq(DD / 256, MM / 128, 3);   // (4, 32, 3) fused QKV
    gemm_cp<<<gq, 256, GSM_BYTES>>>(bq, bk, bv, bo, nullptr, 0);

    repack_kv<<<8192, 256>>>();

    flash_mma<<<dim3(SS / 128, BB * HH), 256, FSM_BYTES>>>();

    dim3 go(DD / 256, MM / 128, 1);   // (4, 32)
    gemm_cp<<<go, 256, GSM_BYTES>>>(bq, bk, bv, bo, out, 1);
}